// round 2
// baseline (speedup 1.0000x reference)
#include <cuda_runtime.h>
#include <math.h>

#define BATCH 16
#define CCH   256
#define NSP   4096   // 64*64
#define CSP   32     // C/8
#define NPOOL 1024   // 32*32

// ---------------- scratch (no cudaMalloc allowed) ----------------
__device__ float g_k[BATCH * CSP * NSP];                    //  8 MB
__device__ float g_qfull[BATCH * CSP * NSP];                //  8 MB
__device__ float g_q[BATCH * NPOOL * CSP];                  //  2 MB  (B, Np, Cs)
__device__ float g_vfull[(size_t)BATCH * CCH * NSP];        // 64 MB
__device__ float g_vpool[BATCH * CCH * NPOOL];              // 16 MB
__device__ float g_vprime[BATCH * CCH * NPOOL];             // 16 MB  v' = wo @ v_pool
__device__ float g_attn[(size_t)BATCH * NPOOL * NSP];       // 256 MB

// ---------------- generic tiled fp32 GEMM ----------------
// C[b] = A(row-major MxK, optionally batched) @ B[b](row-major KxN) (+bias)
// EPI==1: C = gamma*(acc + bias) + xres   (final residual epilogue)
template<int BM, int BN, int BK, int TM, int TN, bool ABATCH, int EPI>
__global__ void gemm_k(const float* __restrict__ A,
                       const float* __restrict__ B,
                       const float* __restrict__ bias,
                       float* __restrict__ C,
                       int M, int N, int K,
                       const float* __restrict__ xres,
                       const float* __restrict__ gamma)
{
    constexpr int THREADS = (BM / TM) * (BN / TN);
    const int b = blockIdx.z;
    const float* Ab = ABATCH ? A + (size_t)b * M * K : A;
    const float* Bb = B + (size_t)b * K * N;
    float* Cb = C + (size_t)b * M * N;

    __shared__ float As[BK][BM + 1];   // +1 pad: avoid 16-way store conflicts
    __shared__ float Bs[BK][BN];

    const int tid  = threadIdx.x;
    const int tcol = tid % (BN / TN);
    const int trow = tid / (BN / TN);
    const int row0 = blockIdx.y * BM;
    const int col0 = blockIdx.x * BN;

    float acc[TM][TN];
#pragma unroll
    for (int i = 0; i < TM; i++)
#pragma unroll
        for (int j = 0; j < TN; j++) acc[i][j] = 0.f;

    for (int k0 = 0; k0 < K; k0 += BK) {
#pragma unroll
        for (int i = tid; i < BM * BK; i += THREADS) {
            int r = i / BK, c = i % BK;
            As[c][r] = Ab[(size_t)(row0 + r) * K + k0 + c];
        }
#pragma unroll
        for (int i = tid; i < BK * BN; i += THREADS) {
            int r = i / BN, c = i % BN;
            Bs[r][c] = Bb[(size_t)(k0 + r) * N + col0 + c];
        }
        __syncthreads();
#pragma unroll
        for (int kk = 0; kk < BK; kk++) {
            float ar[TM], br[TN];
#pragma unroll
            for (int i = 0; i < TM; i++) ar[i] = As[kk][trow * TM + i];
#pragma unroll
            for (int j = 0; j < TN; j++) br[j] = Bs[kk][tcol * TN + j];
#pragma unroll
            for (int i = 0; i < TM; i++)
#pragma unroll
                for (int j = 0; j < TN; j++) acc[i][j] += ar[i] * br[j];
        }
        __syncthreads();
    }

    const float g = (EPI == 1) ? gamma[0] : 0.f;
#pragma unroll
    for (int i = 0; i < TM; i++) {
        int r = row0 + trow * TM + i;
        float bv = (bias != nullptr) ? bias[r] : 0.f;
#pragma unroll
        for (int j = 0; j < TN; j++) {
            int cc = col0 + tcol * TN + j;
            float v = acc[i][j] + bv;
            if (EPI == 1)
                v = g * v + xres[(size_t)b * M * N + (size_t)r * N + cc];
            Cb[(size_t)r * N + cc] = v;
        }
    }
}

// ---------------- maxpool 2x2 stride 2 ----------------
// qfull (B, Cs, 64, 64) -> q (B, Np, Cs)   [transposed for energy GEMM]
__global__ void pool_q_k(const float* __restrict__ qf, float* __restrict__ q)
{
    int idx = blockIdx.x * 256 + threadIdx.x;          // b|np|cs
    if (idx >= BATCH * NPOOL * CSP) return;
    int cs = idx & 31;
    int np = (idx >> 5) & 1023;
    int b  = idx >> 15;
    int ph = np >> 5, pw = np & 31;
    const float* base = qf + ((size_t)b * CSP + cs) * NSP + (2 * ph) * 64 + 2 * pw;
    q[idx] = fmaxf(fmaxf(base[0], base[1]), fmaxf(base[64], base[65]));
}

// vfull (B, C, 64, 64) -> vpool (B, C, Np)
__global__ void pool_v_k(const float* __restrict__ vf, float* __restrict__ vp)
{
    int idx = blockIdx.x * 256 + threadIdx.x;          // (b*256+c)*1024+np
    if (idx >= BATCH * CCH * NPOOL) return;
    int np = idx & 1023;
    int c  = (idx >> 10) & 255;
    int b  = idx >> 18;
    int ph = np >> 5, pw = np & 31;
    const float* base = vf + ((size_t)b * CCH + c) * NSP + (2 * ph) * 64 + 2 * pw;
    vp[idx] = fmaxf(fmaxf(base[0], base[1]), fmaxf(base[64], base[65]));
}

// ---------------- row softmax over last dim (4096), in-place ----------------
__global__ void softmax_k(float* __restrict__ attn)
{
    __shared__ float es[NSP];
    __shared__ float red[8];
    const size_t row = blockIdx.x;
    float* p = attn + row * NSP;
    const int tid = threadIdx.x;

    float lm = -1e30f;
    for (int m = tid; m < NSP; m += 256) {
        float v = p[m];
        es[m] = v;
        lm = fmaxf(lm, v);
    }
#pragma unroll
    for (int o = 16; o; o >>= 1) lm = fmaxf(lm, __shfl_xor_sync(0xffffffffu, lm, o));
    if ((tid & 31) == 0) red[tid >> 5] = lm;
    __syncthreads();
    float bm = red[0];
#pragma unroll
    for (int i = 1; i < 8; i++) bm = fmaxf(bm, red[i]);
    __syncthreads();   // protect red before reuse

    float ls = 0.f;
    for (int m = tid; m < NSP; m += 256) {
        float v = __expf(es[m] - bm);
        es[m] = v;
        ls += v;
    }
#pragma unroll
    for (int o = 16; o; o >>= 1) ls += __shfl_xor_sync(0xffffffffu, ls, o);
    if ((tid & 31) == 0) red[tid >> 5] = ls;
    __syncthreads();
    float bs = 0.f;
#pragma unroll
    for (int i = 0; i < 8; i++) bs += red[i];
    const float inv = 1.f / bs;
    for (int m = tid; m < NSP; m += 256) p[m] = es[m] * inv;
}

// ---------------- launch ----------------
extern "C" void kernel_launch(void* const* d_in, const int* in_sizes, int n_in,
                              void* d_out, int out_size)
{
    const float* x     = (const float*)d_in[0];
    const float* wq    = (const float*)d_in[1];
    const float* bq    = (const float*)d_in[2];
    const float* wk    = (const float*)d_in[3];
    const float* bk    = (const float*)d_in[4];
    const float* wv    = (const float*)d_in[5];
    const float* bv    = (const float*)d_in[6];
    const float* wo    = (const float*)d_in[7];
    const float* bo    = (const float*)d_in[8];
    const float* gamma = (const float*)d_in[9];
    float* out = (float*)d_out;

    float *pk, *pqf, *pq, *pvf, *pvp, *pvpr, *pattn;
    cudaGetSymbolAddress((void**)&pk,    g_k);
    cudaGetSymbolAddress((void**)&pqf,   g_qfull);
    cudaGetSymbolAddress((void**)&pq,    g_q);
    cudaGetSymbolAddress((void**)&pvf,   g_vfull);
    cudaGetSymbolAddress((void**)&pvp,   g_vpool);
    cudaGetSymbolAddress((void**)&pvpr,  g_vprime);
    cudaGetSymbolAddress((void**)&pattn, g_attn);

    // K = wk @ x + bk            (B, 32, 4096)
    {
        dim3 g(NSP / 64, 1, BATCH);
        gemm_k<32, 64, 16, 4, 4, false, 0><<<g, 128>>>(wk, x, bk, pk, CSP, NSP, CCH, nullptr, nullptr);
    }
    // qfull = wq @ x + bq        (B, 32, 4096)
    {
        dim3 g(NSP / 64, 1, BATCH);
        gemm_k<32, 64, 16, 4, 4, false, 0><<<g, 128>>>(wq, x, bq, pqf, CSP, NSP, CCH, nullptr, nullptr);
    }
    // q = maxpool(qfull) transposed -> (B, Np, Cs)
    pool_q_k<<<(BATCH * NPOOL * CSP) / 256, 256>>>(pqf, pq);

    // vfull = wv @ x + bv        (B, 256, 4096)
    {
        dim3 g(NSP / 64, CCH / 64, BATCH);
        gemm_k<64, 64, 16, 4, 4, false, 0><<<g, 256>>>(wv, x, bv, pvf, CCH, NSP, CCH, nullptr, nullptr);
    }
    // vpool = maxpool(vfull)     (B, 256, 1024)
    pool_v_k<<<(BATCH * CCH * NPOOL) / 256, 256>>>(pvf, pvp);

    // v' = wo @ vpool (no bias — bo applied in final epilogue)
    {
        dim3 g(NPOOL / 64, CCH / 64, BATCH);
        gemm_k<64, 64, 16, 4, 4, false, 0><<<g, 256>>>(wo, pvp, nullptr, pvpr, CCH, NPOOL, CCH, nullptr, nullptr);
    }
    // energy = q @ k             (B, 1024, 4096)
    {
        dim3 g(NSP / 64, NPOOL / 64, BATCH);
        gemm_k<64, 64, 16, 4, 4, true, 0><<<g, 256>>>(pq, pk, nullptr, pattn, NPOOL, NSP, CSP, nullptr, nullptr);
    }
    // softmax rows (in-place)
    softmax_k<<<BATCH * NPOOL, 256>>>(pattn);

    // final = gamma*(v' @ attn + bo) + x   -> d_out (B, 256, 4096)
    {
        dim3 g(NSP / 64, CCH / 64, BATCH);
        gemm_k<64, 64, 16, 4, 4, true, 1><<<g, 256>>>(pvpr, pattn, bo, out, CCH, NSP, NPOOL, x, gamma);
    }
}

// round 3
// speedup vs baseline: 1.3974x; 1.3974x over previous
#include <cuda_runtime.h>
#include <math.h>

#define BATCH 16
#define CCH   256
#define NSP   4096   // 64*64
#define CSP   32     // C/8
#define NPOOL 1024   // 32*32

// ---------------- scratch (no cudaMalloc allowed) ----------------
__device__ float g_k[BATCH * CSP * NSP];                    //  8 MB
__device__ float g_qfull[BATCH * CSP * NSP];                //  8 MB
__device__ float g_q[BATCH * NPOOL * CSP];                  //  2 MB  (B, Np, Cs)
__device__ float g_vfull[(size_t)BATCH * CCH * NSP];        // 64 MB
__device__ float g_vpool[BATCH * CCH * NPOOL];              // 16 MB
__device__ float g_vprime[BATCH * CCH * NPOOL];             // 16 MB  v' = wo @ v_pool
__device__ float g_attn[(size_t)BATCH * NPOOL * NSP];       // 256 MB

// ---------------- v1 GEMM (small-M cases: conv_q / conv_k) ----------------
template<int BM, int BN, int BK, int TM, int TN, bool ABATCH>
__global__ void gemm_k(const float* __restrict__ A,
                       const float* __restrict__ B,
                       const float* __restrict__ bias,
                       float* __restrict__ C,
                       int M, int N, int K)
{
    constexpr int THREADS = (BM / TM) * (BN / TN);
    const int b = blockIdx.z;
    const float* Ab = ABATCH ? A + (size_t)b * M * K : A;
    const float* Bb = B + (size_t)b * K * N;
    float* Cb = C + (size_t)b * M * N;

    __shared__ float As[BK][BM + 1];
    __shared__ float Bs[BK][BN];

    const int tid  = threadIdx.x;
    const int tcol = tid % (BN / TN);
    const int trow = tid / (BN / TN);
    const int row0 = blockIdx.y * BM;
    const int col0 = blockIdx.x * BN;

    float acc[TM][TN] = {};

    for (int k0 = 0; k0 < K; k0 += BK) {
#pragma unroll
        for (int i = tid; i < BM * BK; i += THREADS) {
            int r = i / BK, c = i % BK;
            As[c][r] = Ab[(size_t)(row0 + r) * K + k0 + c];
        }
#pragma unroll
        for (int i = tid; i < BK * BN; i += THREADS) {
            int r = i / BN, c = i % BN;
            Bs[r][c] = Bb[(size_t)(k0 + r) * N + col0 + c];
        }
        __syncthreads();
#pragma unroll
        for (int kk = 0; kk < BK; kk++) {
            float ar[TM], br[TN];
#pragma unroll
            for (int i = 0; i < TM; i++) ar[i] = As[kk][trow * TM + i];
#pragma unroll
            for (int j = 0; j < TN; j++) br[j] = Bs[kk][tcol * TN + j];
#pragma unroll
            for (int i = 0; i < TM; i++)
#pragma unroll
                for (int j = 0; j < TN; j++) acc[i][j] += ar[i] * br[j];
        }
        __syncthreads();
    }

#pragma unroll
    for (int i = 0; i < TM; i++) {
        int r = row0 + trow * TM + i;
        float bv = (bias != nullptr) ? bias[r] : 0.f;
#pragma unroll
        for (int j = 0; j < TN; j++) {
            int cc = col0 + tcol * TN + j;
            Cb[(size_t)r * N + cc] = acc[i][j] + bv;
        }
    }
}

// ---------------- v2 GEMM: 128x128 tile, 8x8 microtile, float4 I/O ----------
// EPI==1: C = gamma*(acc + bias) + xres
template<bool ABATCH, int EPI>
__global__ __launch_bounds__(256, 2)
void gemm2(const float* __restrict__ A,
           const float* __restrict__ B,
           const float* __restrict__ bias,
           float* __restrict__ C,
           int M, int N, int K,
           const float* __restrict__ xres,
           const float* __restrict__ gamma)
{
    constexpr int BM = 128, BN = 128, BK = 8, TM = 8, TN = 8;
    constexpr int THREADS = 256;

    __shared__ float As[BK][BM + 4];   // rows stay 16B-aligned ((128+4)*4 = 528)
    __shared__ float Bs[BK][BN];

    const int b = blockIdx.z;
    const float* Ab = ABATCH ? A + (size_t)b * M * K : A;
    const float* Bb = B + (size_t)b * K * N;
    float* Cb = C + (size_t)b * M * N;

    const int tid  = threadIdx.x;
    const int tcol = tid & 15;          // 0..15
    const int trow = tid >> 4;          // 0..15
    const int row0 = blockIdx.y * BM;
    const int col0 = blockIdx.x * BN;

    // A tile: 128x8 = 256 float4 (one per thread), stored transposed
    const int a_r  = tid >> 1;          // 0..127
    const int a_kq = (tid & 1) * 4;     // 0 or 4
    // B tile: 8x128 = 256 float4 (one per thread)
    const int b_r  = tid >> 5;          // 0..7
    const int b_c  = (tid & 31) * 4;    // 0..124

    float acc[TM][TN] = {};

    for (int k0 = 0; k0 < K; k0 += BK) {
        float4 av = *(const float4*)&Ab[(size_t)(row0 + a_r) * K + k0 + a_kq];
        As[a_kq + 0][a_r] = av.x;
        As[a_kq + 1][a_r] = av.y;
        As[a_kq + 2][a_r] = av.z;
        As[a_kq + 3][a_r] = av.w;
        *(float4*)&Bs[b_r][b_c] = *(const float4*)&Bb[(size_t)(k0 + b_r) * N + col0 + b_c];
        __syncthreads();

#pragma unroll
        for (int kk = 0; kk < BK; kk++) {
            float ar[TM], br[TN];
            *(float4*)&ar[0] = *(const float4*)&As[kk][trow * TM + 0];
            *(float4*)&ar[4] = *(const float4*)&As[kk][trow * TM + 4];
            *(float4*)&br[0] = *(const float4*)&Bs[kk][tcol * TN + 0];
            *(float4*)&br[4] = *(const float4*)&Bs[kk][tcol * TN + 4];
#pragma unroll
            for (int i = 0; i < TM; i++)
#pragma unroll
                for (int j = 0; j < TN; j++) acc[i][j] += ar[i] * br[j];
        }
        __syncthreads();
    }

    const float g = (EPI == 1) ? gamma[0] : 0.f;
#pragma unroll
    for (int i = 0; i < TM; i++) {
        const int r = row0 + trow * TM + i;
        const float bv = (bias != nullptr) ? bias[r] : 0.f;
        const size_t rowoff = (size_t)r * N;
#pragma unroll
        for (int jq = 0; jq < TN; jq += 4) {
            const int cc = col0 + tcol * TN + jq;
            float4 o;
            o.x = acc[i][jq + 0] + bv;
            o.y = acc[i][jq + 1] + bv;
            o.z = acc[i][jq + 2] + bv;
            o.w = acc[i][jq + 3] + bv;
            if (EPI == 1) {
                const float4 xr = *(const float4*)&xres[(size_t)b * M * N + rowoff + cc];
                o.x = g * o.x + xr.x;
                o.y = g * o.y + xr.y;
                o.z = g * o.z + xr.z;
                o.w = g * o.w + xr.w;
            }
            *(float4*)&Cb[rowoff + cc] = o;
        }
    }
}

// ---------------- maxpool 2x2 stride 2 ----------------
__global__ void pool_q_k(const float* __restrict__ qf, float* __restrict__ q)
{
    int idx = blockIdx.x * 256 + threadIdx.x;          // b|np|cs
    if (idx >= BATCH * NPOOL * CSP) return;
    int cs = idx & 31;
    int np = (idx >> 5) & 1023;
    int b  = idx >> 15;
    int ph = np >> 5, pw = np & 31;
    const float* base = qf + ((size_t)b * CSP + cs) * NSP + (2 * ph) * 64 + 2 * pw;
    q[idx] = fmaxf(fmaxf(base[0], base[1]), fmaxf(base[64], base[65]));
}

__global__ void pool_v_k(const float* __restrict__ vf, float* __restrict__ vp)
{
    int idx = blockIdx.x * 256 + threadIdx.x;          // (b*256+c)*1024+np
    if (idx >= BATCH * CCH * NPOOL) return;
    int np = idx & 1023;
    int c  = (idx >> 10) & 255;
    int b  = idx >> 18;
    int ph = np >> 5, pw = np & 31;
    const float* base = vf + ((size_t)b * CCH + c) * NSP + (2 * ph) * 64 + 2 * pw;
    vp[idx] = fmaxf(fmaxf(base[0], base[1]), fmaxf(base[64], base[65]));
}

// ---------------- row softmax over last dim (4096), in-place ----------------
__global__ void softmax_k(float* __restrict__ attn)
{
    __shared__ float es[NSP];
    __shared__ float red[8];
    const size_t row = blockIdx.x;
    float* p = attn + row * NSP;
    const int tid = threadIdx.x;

    float lm = -1e30f;
    for (int m = tid; m < NSP; m += 256) {
        float v = p[m];
        es[m] = v;
        lm = fmaxf(lm, v);
    }
#pragma unroll
    for (int o = 16; o; o >>= 1) lm = fmaxf(lm, __shfl_xor_sync(0xffffffffu, lm, o));
    if ((tid & 31) == 0) red[tid >> 5] = lm;
    __syncthreads();
    float bm = red[0];
#pragma unroll
    for (int i = 1; i < 8; i++) bm = fmaxf(bm, red[i]);
    __syncthreads();

    float ls = 0.f;
    for (int m = tid; m < NSP; m += 256) {
        float v = __expf(es[m] - bm);
        es[m] = v;
        ls += v;
    }
#pragma unroll
    for (int o = 16; o; o >>= 1) ls += __shfl_xor_sync(0xffffffffu, ls, o);
    if ((tid & 31) == 0) red[tid >> 5] = ls;
    __syncthreads();
    float bs = 0.f;
#pragma unroll
    for (int i = 0; i < 8; i++) bs += red[i];
    const float inv = 1.f / bs;
    for (int m = tid; m < NSP; m += 256) p[m] = es[m] * inv;
}

// ---------------- launch ----------------
extern "C" void kernel_launch(void* const* d_in, const int* in_sizes, int n_in,
                              void* d_out, int out_size)
{
    const float* x     = (const float*)d_in[0];
    const float* wq    = (const float*)d_in[1];
    const float* bq    = (const float*)d_in[2];
    const float* wk    = (const float*)d_in[3];
    const float* bk    = (const float*)d_in[4];
    const float* wv    = (const float*)d_in[5];
    const float* bv    = (const float*)d_in[6];
    const float* wo    = (const float*)d_in[7];
    const float* bo    = (const float*)d_in[8];
    const float* gamma = (const float*)d_in[9];
    float* out = (float*)d_out;

    float *pk, *pqf, *pq, *pvf, *pvp, *pvpr, *pattn;
    cudaGetSymbolAddress((void**)&pk,    g_k);
    cudaGetSymbolAddress((void**)&pqf,   g_qfull);
    cudaGetSymbolAddress((void**)&pq,    g_q);
    cudaGetSymbolAddress((void**)&pvf,   g_vfull);
    cudaGetSymbolAddress((void**)&pvp,   g_vpool);
    cudaGetSymbolAddress((void**)&pvpr,  g_vprime);
    cudaGetSymbolAddress((void**)&pattn, g_attn);

    // One-time stream/event creation (host resources, created outside capture
    // on the correctness call; reused on the capture call).
    static cudaStream_t s1 = nullptr;
    static cudaEvent_t evFork = nullptr, evJoin = nullptr;
    if (s1 == nullptr) {
        cudaStreamCreateWithFlags(&s1, cudaStreamNonBlocking);
        cudaEventCreateWithFlags(&evFork, cudaEventDisableTiming);
        cudaEventCreateWithFlags(&evJoin, cudaEventDisableTiming);
    }

    // Fork: V branch on s1, QK/energy/softmax chain on the default stream.
    cudaEventRecord(evFork, 0);
    cudaStreamWaitEvent(s1, evFork, 0);

    // --- s1: V branch ---
    {   // vfull = wv @ x + bv        (B, 256, 4096)
        dim3 g(NSP / 128, CCH / 128, BATCH);
        gemm2<false, 0><<<g, 256, 0, s1>>>(wv, x, bv, pvf, CCH, NSP, CCH, nullptr, nullptr);
    }
    pool_v_k<<<(BATCH * CCH * NPOOL) / 256, 256, 0, s1>>>(pvf, pvp);
    {   // v' = wo @ vpool (bias bo folded into final epilogue)
        dim3 g(NPOOL / 128, CCH / 128, BATCH);
        gemm2<false, 0><<<g, 256, 0, s1>>>(wo, pvp, nullptr, pvpr, CCH, NPOOL, CCH, nullptr, nullptr);
    }
    cudaEventRecord(evJoin, s1);

    // --- default stream: Q/K -> energy -> softmax ---
    {   // K = wk @ x + bk            (B, 32, 4096)
        dim3 g(NSP / 64, 1, BATCH);
        gemm_k<32, 64, 16, 4, 4, false><<<g, 128>>>(wk, x, bk, pk, CSP, NSP, CCH);
    }
    {   // qfull = wq @ x + bq        (B, 32, 4096)
        dim3 g(NSP / 64, 1, BATCH);
        gemm_k<32, 64, 16, 4, 4, false><<<g, 128>>>(wq, x, bq, pqf, CSP, NSP, CCH);
    }
    pool_q_k<<<(BATCH * NPOOL * CSP) / 256, 256>>>(pqf, pq);
    {   // energy = q @ k             (B, 1024, 4096)
        dim3 g(NSP / 128, NPOOL / 128, BATCH);
        gemm2<true, 0><<<g, 256>>>(pq, pk, nullptr, pattn, NPOOL, NSP, CSP, nullptr, nullptr);
    }
    softmax_k<<<BATCH * NPOOL, 256>>>(pattn);

    // Join, then final = gamma*(v' @ attn + bo) + x   -> (B, 256, 4096)
    cudaStreamWaitEvent(0, evJoin, 0);
    {
        dim3 g(NSP / 128, CCH / 128, BATCH);
        gemm2<true, 1><<<g, 256>>>(pvpr, pattn, bo, out, CCH, NSP, NPOOL, x, gamma);
    }
}

// round 5
// speedup vs baseline: 3.0973x; 2.2164x over previous
#include <cuda_runtime.h>
#include <math.h>
#include <stdint.h>

#define BATCH 16
#define CCH   256
#define NSP   4096   // 64*64
#define CSP   32     // C/8
#define NPOOL 1024   // 32*32

// ---------------- scratch ----------------
__device__ float g_kT[BATCH * NSP * CSP];                   //  8 MB  (B, N, Cs)
__device__ float g_qT[BATCH * CSP * NPOOL];                 //  2 MB  (B, Cs, Np)
__device__ float g_vpool[BATCH * CCH * NPOOL];              // 16 MB
__device__ float g_vprime[BATCH * CCH * NPOOL];             // 16 MB  v' = wo @ vpool (then /denom)
__device__ float g_part[BATCH * 32 * NPOOL];                //  2 MB  per-mblock column sums
__device__ float g_invden[BATCH * NPOOL];                   // 64 KB
__device__ float g_attn[(size_t)BATCH * NSP * NPOOL];       // 256 MB (B, N, Np): exp(E), tf32

// ---------------- helpers ----------------
__device__ __forceinline__ float tf32_rn(float v) {
    uint32_t u;
    asm("cvt.rna.tf32.f32 %0, %1;" : "=r"(u) : "f"(v));
    return __uint_as_float(u);
}

// ---------------- fused conv_q + conv_k (+ q maxpool) ----------------
// Produces kT (B, 4096, 32) and pooled qT (B, 32, 1024).
__global__ __launch_bounds__(256)
void conv_qk_k(const float* __restrict__ wk, const float* __restrict__ bk,
               const float* __restrict__ wq, const float* __restrict__ bq,
               const float* __restrict__ x,
               float* __restrict__ kT, float* __restrict__ qT)
{
    __shared__ float As[16][68];
    __shared__ float Bs[16][128];
    __shared__ float Ks[32][132];
    __shared__ float Qs[32][128];

    const int b    = blockIdx.z;
    const int col0 = blockIdx.x * 128;
    const float* Bb = x + (size_t)b * CCH * NSP;
    const int tid  = threadIdx.x;
    const int tcol = tid & 15;
    const int trow = tid >> 4;

    const int a_r = tid >> 2;                          // 0..63
    const int a_k = (tid & 3) * 4;
    const float* wrow = (a_r < 32) ? (wk + a_r * CCH) : (wq + (a_r - 32) * CCH);

    float acc[4][8] = {};

    for (int k0 = 0; k0 < CCH; k0 += 16) {
        float4 av = *(const float4*)&wrow[k0 + a_k];
        As[a_k + 0][a_r] = av.x;
        As[a_k + 1][a_r] = av.y;
        As[a_k + 2][a_r] = av.z;
        As[a_k + 3][a_r] = av.w;
#pragma unroll
        for (int i = 0; i < 2; i++) {
            int idx = tid + i * 256;
            int br = idx >> 5, bc = (idx & 31) * 4;
            *(float4*)&Bs[br][bc] = *(const float4*)&Bb[(size_t)(k0 + br) * NSP + col0 + bc];
        }
        __syncthreads();
#pragma unroll
        for (int kk = 0; kk < 16; kk++) {
            float ar[4], br[8];
            *(float4*)&ar[0] = *(const float4*)&As[kk][trow * 4];
            *(float4*)&br[0] = *(const float4*)&Bs[kk][tcol * 8 + 0];
            *(float4*)&br[4] = *(const float4*)&Bs[kk][tcol * 8 + 4];
#pragma unroll
            for (int i = 0; i < 4; i++)
#pragma unroll
                for (int j = 0; j < 8; j++) acc[i][j] += ar[i] * br[j];
        }
        __syncthreads();
    }

#pragma unroll
    for (int i = 0; i < 4; i++) {
        int r2 = trow * 4 + i;
        float bb = (r2 < 32) ? bk[r2] : bq[r2 - 32];
        if (r2 < 32) {
#pragma unroll
            for (int j = 0; j < 8; j++) Ks[r2][tcol * 8 + j] = acc[i][j] + bb;
        } else {
#pragma unroll
            for (int j = 0; j < 8; j++) Qs[r2 - 32][tcol * 8 + j] = acc[i][j] + bb;
        }
    }
    __syncthreads();

    float* kTb = kT + (size_t)b * NSP * CSP;
#pragma unroll
    for (int i = 0; i < 4; i++) {
        int idx = tid + i * 256;
        int mm = idx >> 3, cq = (idx & 7) * 4;
        float4 o;
        o.x = Ks[cq + 0][mm];
        o.y = Ks[cq + 1][mm];
        o.z = Ks[cq + 2][mm];
        o.w = Ks[cq + 3][mm];
        *(float4*)&kTb[(size_t)(col0 + mm) * CSP + cq] = o;
    }

    float* qTb = qT + (size_t)b * CSP * NPOOL;
    const int hp = col0 >> 7;
#pragma unroll
    for (int i = 0; i < 4; i++) {
        int idx = tid + i * 256;
        int cs = idx >> 5, wp = idx & 31;
        float v = fmaxf(fmaxf(Qs[cs][2 * wp], Qs[cs][2 * wp + 1]),
                        fmaxf(Qs[cs][64 + 2 * wp], Qs[cs][64 + 2 * wp + 1]));
        qTb[cs * NPOOL + hp * 32 + wp] = v;
    }
}

// ---------------- fp32 GEMM: 128x128 tile, 8x8 micro, float4 I/O ----------
// EPI==0: C = acc + bias
// EPI==3: C = tf32(exp(acc)); per-column (N-dim) sums of exp into
//         part[(b*32 + blockIdx.y)*N + col]   (energy+softmax-numerator)
// EPI==4: 2x2 maxpool epilogue: C treated as (B, M, N/4) pooled output
template<bool ABATCH, int EPI>
__global__ __launch_bounds__(256, 2)
void gemm2(const float* __restrict__ A,
           const float* __restrict__ B,
           const float* __restrict__ bias,
           float* __restrict__ C,
           int M, int N, int K,
           float* __restrict__ part)
{
    constexpr int BM = 128, BN = 128, BK = 8;

    __shared__ float As[BK][BM + 4];
    __shared__ float Bs[BK][BN];
    __shared__ float red[(EPI == 3) ? 16 : 1][(EPI == 3) ? 132 : 1];

    const int b = blockIdx.z;
    const float* Ab = ABATCH ? A + (size_t)b * M * K : A;
    const float* Bb = B + (size_t)b * K * N;

    const int tid  = threadIdx.x;
    const int tcol = tid & 15;
    const int trow = tid >> 4;
    const int row0 = blockIdx.y * BM;
    const int col0 = blockIdx.x * BN;

    const int a_r  = tid >> 1;
    const int a_kq = (tid & 1) * 4;
    const int b_r  = tid >> 5;
    const int b_c  = (tid & 31) * 4;

    float acc[8][8] = {};

    for (int k0 = 0; k0 < K; k0 += BK) {
        float4 av = *(const float4*)&Ab[(size_t)(row0 + a_r) * K + k0 + a_kq];
        As[a_kq + 0][a_r] = av.x;
        As[a_kq + 1][a_r] = av.y;
        As[a_kq + 2][a_r] = av.z;
        As[a_kq + 3][a_r] = av.w;
        *(float4*)&Bs[b_r][b_c] = *(const float4*)&Bb[(size_t)(k0 + b_r) * N + col0 + b_c];
        __syncthreads();
#pragma unroll
        for (int kk = 0; kk < BK; kk++) {
            float ar[8], br[8];
            *(float4*)&ar[0] = *(const float4*)&As[kk][trow * 8 + 0];
            *(float4*)&ar[4] = *(const float4*)&As[kk][trow * 8 + 4];
            *(float4*)&br[0] = *(const float4*)&Bs[kk][tcol * 8 + 0];
            *(float4*)&br[4] = *(const float4*)&Bs[kk][tcol * 8 + 4];
#pragma unroll
            for (int i = 0; i < 8; i++)
#pragma unroll
                for (int j = 0; j < 8; j++) acc[i][j] += ar[i] * br[j];
        }
        __syncthreads();
    }

    if (EPI == 4) {
        // 2x2 maxpool: tile columns cover two image rows (N tile = 128 = 2*64).
        // Horizontal pair (j, j+1) in-thread; vertical partner is col+64 ->
        // thread tcol+8 -> lane^8.
        float* Cp = C + (size_t)b * M * (N / 4);   // pooled (M, N/4)
        const int bx = blockIdx.x;                 // pooled row ph
#pragma unroll
        for (int i = 0; i < 8; i++) {
            const int r = row0 + trow * 8 + i;
            const float bv = bias[r];
#pragma unroll
            for (int j = 0; j < 8; j += 2) {
                float m2 = fmaxf(acc[i][j], acc[i][j + 1]);
                float mo = __shfl_xor_sync(0xffffffffu, m2, 8);
                if (tcol < 8) {
                    Cp[(size_t)r * (N / 4) + bx * 32 + tcol * 4 + (j >> 1)] =
                        fmaxf(m2, mo) + bv;
                }
            }
        }
        return;
    }

    if (EPI == 3) {
        float* Cb = C + (size_t)b * M * N;
        float s[8] = {};
#pragma unroll
        for (int i = 0; i < 8; i++) {
            const int r = row0 + trow * 8 + i;
            const size_t rowoff = (size_t)r * N;
#pragma unroll
            for (int jq = 0; jq < 8; jq += 4) {
                const int cc = col0 + tcol * 8 + jq;
                float e0 = __expf(acc[i][jq + 0]);
                float e1 = __expf(acc[i][jq + 1]);
                float e2 = __expf(acc[i][jq + 2]);
                float e3 = __expf(acc[i][jq + 3]);
                s[jq + 0] += e0; s[jq + 1] += e1;
                s[jq + 2] += e2; s[jq + 3] += e3;
                float4 o;
                o.x = tf32_rn(e0); o.y = tf32_rn(e1);
                o.z = tf32_rn(e2); o.w = tf32_rn(e3);
                *(float4*)&Cb[rowoff + cc] = o;
            }
        }
#pragma unroll
        for (int j = 0; j < 8; j++) red[trow][tcol * 8 + j] = s[j];
        __syncthreads();
        if (tid < 128) {
            float t = 0.f;
#pragma unroll
            for (int k = 0; k < 16; k++) t += red[k][tid];
            part[((size_t)b * 32 + blockIdx.y) * N + col0 + tid] = t;
        }
        return;
    }

    // EPI == 0
    float* Cb = C + (size_t)b * M * N;
#pragma unroll
    for (int i = 0; i < 8; i++) {
        const int r = row0 + trow * 8 + i;
        const float bv = (bias != nullptr) ? bias[r] : 0.f;
        const size_t rowoff = (size_t)r * N;
#pragma unroll
        for (int jq = 0; jq < 8; jq += 4) {
            const int cc = col0 + tcol * 8 + jq;
            float4 o;
            o.x = acc[i][jq + 0] + bv;
            o.y = acc[i][jq + 1] + bv;
            o.z = acc[i][jq + 2] + bv;
            o.w = acc[i][jq + 3] + bv;
            *(float4*)&Cb[rowoff + cc] = o;
        }
    }
}

// ---------------- denominator: sum 32 partials per (b, np) ----------------
__global__ void invden_k(const float* __restrict__ part, float* __restrict__ invden)
{
    int idx = blockIdx.x * 256 + threadIdx.x;     // 16*1024 total
    int b  = idx >> 10;
    int np = idx & 1023;
    const float* p = part + (size_t)b * 32 * NPOOL + np;
    float s = 0.f;
#pragma unroll
    for (int i = 0; i < 32; i++) s += p[(size_t)i * NPOOL];
    invden[idx] = 1.f / s;
}

// ---------------- v'' = tf32(v' / denom[np]) in place ----------------
__global__ void scale_v_k(float* __restrict__ vpr, const float* __restrict__ invden)
{
    int idx = blockIdx.x * 256 + threadIdx.x;     // B*CCH*NPOOL
    int np = idx & 1023;
    int b  = idx >> 18;
    vpr[idx] = tf32_rn(vpr[idx] * invden[b * NPOOL + np]);
}

// ---------------- final GEMM: mma.sync tf32 ----------------
// out[c][m] = gamma*( sum_np v''[c][np] * p[m][np] + bo[c] ) + x[c][m]
__global__ __launch_bounds__(256)
void final_mma_k(const float* __restrict__ vpp,
                 const float* __restrict__ pm,
                 const float* __restrict__ bo,
                 const float* __restrict__ gamma,
                 const float* __restrict__ xres,
                 float* __restrict__ out)
{
    __shared__ float sA[128 * 36];
    __shared__ float sB[128 * 36];

    const int tid  = threadIdx.x;
    const int lane = tid & 31;
    const int wid  = tid >> 5;
    const int b  = blockIdx.z;
    const int c0 = blockIdx.y * 128;
    const int m0 = blockIdx.x * 128;
    const int wr = wid >> 2;            // 0..1  (c dim, 64 rows)
    const int wc = wid & 3;             // 0..3  (m dim, 32 cols)
    const int g  = lane >> 2;           // 0..7
    const int tk = lane & 3;            // 0..3

    const float* Ab = vpp + ((size_t)b * CCH + c0) * NPOOL;
    const float* Bb = pm  + ((size_t)b * NSP + m0) * NPOOL;

    float cf[4][4][4] = {};

    for (int kt = 0; kt < NPOOL / 32; kt++) {
        const int kb = kt * 32;
#pragma unroll
        for (int u = 0; u < 4; u++) {
            int idx = tid + u * 256;
            int r = idx >> 3, cq = idx & 7;
            *(float4*)&sA[r * 36 + cq * 4] = *(const float4*)&Ab[(size_t)r * NPOOL + kb + cq * 4];
            *(float4*)&sB[r * 36 + cq * 4] = *(const float4*)&Bb[(size_t)r * NPOOL + kb + cq * 4];
        }
        __syncthreads();
#pragma unroll
        for (int ks = 0; ks < 4; ks++) {
            const int k0 = ks * 8;
            uint32_t a[4][4], bf[4][2];
#pragma unroll
            for (int i = 0; i < 4; i++) {
                const int ra = (wr * 64 + i * 16 + g) * 36 + k0 + tk;
                a[i][0] = __float_as_uint(sA[ra]);
                a[i][1] = __float_as_uint(sA[ra + 8 * 36]);
                a[i][2] = __float_as_uint(sA[ra + 4]);
                a[i][3] = __float_as_uint(sA[ra + 8 * 36 + 4]);
            }
#pragma unroll
            for (int j = 0; j < 4; j++) {
                const int rb = (wc * 32 + j * 8 + g) * 36 + k0 + tk;
                bf[j][0] = __float_as_uint(sB[rb]);
                bf[j][1] = __float_as_uint(sB[rb + 4]);
            }
#pragma unroll
            for (int i = 0; i < 4; i++)
#pragma unroll
                for (int j = 0; j < 4; j++)
                    asm volatile(
                        "mma.sync.aligned.m16n8k8.row.col.f32.tf32.tf32.f32 "
                        "{%0,%1,%2,%3}, {%4,%5,%6,%7}, {%8,%9}, {%0,%1,%2,%3};"
                        : "+f"(cf[i][j][0]), "+f"(cf[i][j][1]),
                          "+f"(cf[i][j][2]), "+f"(cf[i][j][3])
                        : "r"(a[i][0]), "r"(a[i][1]), "r"(a[i][2]), "r"(a[i][3]),
                          "r"(bf[j][0]), "r"(bf[j][1]));
        }
        __syncthreads();
    }

    const float gm = gamma[0];
#pragma unroll
    for (int i = 0; i < 4; i++) {
#pragma unroll
        for (int half = 0; half < 2; half++) {
            const int c = c0 + wr * 64 + i * 16 + g + half * 8;
            const float bc = bo[c];
            const size_t ro = ((size_t)b * CCH + c) * NSP;
#pragma unroll
            for (int j = 0; j < 4; j++) {
                const int m = m0 + wc * 32 + j * 8 + 2 * tk;
                float2 xr = *(const float2*)&xres[ro + m];
                float2 o;
                o.x = gm * (cf[i][j][half * 2 + 0] + bc) + xr.x;
                o.y = gm * (cf[i][j][half * 2 + 1] + bc) + xr.y;
                *(float2*)&out[ro + m] = o;
            }
        }
    }
}

// ---------------- launch ----------------
extern "C" void kernel_launch(void* const* d_in, const int* in_sizes, int n_in,
                              void* d_out, int out_size)
{
    const float* x     = (const float*)d_in[0];
    const float* wq    = (const float*)d_in[1];
    const float* bq    = (const float*)d_in[2];
    const float* wk    = (const float*)d_in[3];
    const float* bk    = (const float*)d_in[4];
    const float* wv    = (const float*)d_in[5];
    const float* bv    = (const float*)d_in[6];
    const float* wo    = (const float*)d_in[7];
    const float* bo    = (const float*)d_in[8];
    const float* gamma = (const float*)d_in[9];
    float* out = (float*)d_out;

    float *pkT, *pqT, *pvp, *pvpr, *ppart, *pinv, *pattn;
    cudaGetSymbolAddress((void**)&pkT,   g_kT);
    cudaGetSymbolAddress((void**)&pqT,   g_qT);
    cudaGetSymbolAddress((void**)&pvp,   g_vpool);
    cudaGetSymbolAddress((void**)&pvpr,  g_vprime);
    cudaGetSymbolAddress((void**)&ppart, g_part);
    cudaGetSymbolAddress((void**)&pinv,  g_invden);
    cudaGetSymbolAddress((void**)&pattn, g_attn);

    static cudaStream_t s1 = nullptr;
    static cudaEvent_t evFork = nullptr, evJoin = nullptr;
    if (s1 == nullptr) {
        cudaStreamCreateWithFlags(&s1, cudaStreamNonBlocking);
        cudaEventCreateWithFlags(&evFork, cudaEventDisableTiming);
        cudaEventCreateWithFlags(&evJoin, cudaEventDisableTiming);
    }

    cudaEventRecord(evFork, 0);
    cudaStreamWaitEvent(s1, evFork, 0);

    // --- s1: V branch ---
    {   // vpool = maxpool(wv @ x + bv), fused epilogue
        dim3 g(NSP / 128, CCH / 128, BATCH);
        gemm2<false, 4><<<g, 256, 0, s1>>>(wv, x, bv, pvp, CCH, NSP, CCH, nullptr);
    }
    {   // v' = wo @ vpool (bo folded into final epilogue)
        dim3 g(NPOOL / 128, CCH / 128, BATCH);
        gemm2<false, 0><<<g, 256, 0, s1>>>(wo, pvp, nullptr, pvpr, CCH, NPOOL, CCH, nullptr);
    }
    cudaEventRecord(evJoin, s1);

    // --- default stream: conv_qk -> energy(+exp, col partials) -> invden ---
    {
        dim3 g(NSP / 128, 1, BATCH);
        conv_qk_k<<<g, 256>>>(wk, bk, wq, bq, x, pkT, pqT);
    }
    {   // p = tf32(exp(kT @ qT)) in g_attn, partials in g_part
        dim3 g(NPOOL / 128, NSP / 128, BATCH);
        gemm2<true, 3><<<g, 256>>>(pkT, pqT, nullptr, pattn, NSP, NPOOL, CSP, ppart);
    }
    invden_k<<<BATCH * NPOOL / 256, 256>>>(ppart, pinv);

    // join, then fold denom into v', then tensor-core final
    cudaStreamWaitEvent(0, evJoin, 0);
    scale_v_k<<<BATCH * CCH * NPOOL / 256, 256>>>(pvpr, pinv);
    {
        dim3 g(NSP / 128, CCH / 128, BATCH);
        final_mma_k<<<g, 256>>>(pvpr, pattn, bo, gamma, x, out);
    }
}

// round 6
// speedup vs baseline: 4.0965x; 1.3226x over previous
#include <cuda_runtime.h>
#include <cuda_bf16.h>
#include <math.h>
#include <stdint.h>

#define BATCH 16
#define CCH   256
#define NSP   4096   // 64*64
#define CSP   32     // C/8
#define NPOOL 1024   // 32*32

// ---------------- scratch ----------------
__device__ float g_kT[BATCH * NSP * CSP];                    //  8 MB (B, N, Cs)
__device__ float g_qT[BATCH * CSP * NPOOL];                  //  2 MB (B, Cs, Np)
__device__ float g_vpool[BATCH * CCH * NPOOL];               // 16 MB
__device__ float g_vprime[BATCH * CCH * NPOOL];              // 16 MB fp32 v' = wo@vpool
__device__ float g_part[BATCH * 32 * NPOOL];                 //  2 MB column partial sums
__device__ float g_invden[BATCH * NPOOL];                    // 64 KB
__device__ __nv_bfloat16 g_attnh[(size_t)BATCH * NSP * NPOOL]; // 128 MB exp(E) bf16
__device__ __nv_bfloat16 g_vppb[BATCH * CCH * NPOOL];        //  8 MB v'' bf16

// ---------------- helpers ----------------
__device__ __forceinline__ float tf32_rn(float v) {
    uint32_t u;
    asm("cvt.rna.tf32.f32 %0, %1;" : "=r"(u) : "f"(v));
    return __uint_as_float(u);
}

// ---------------- fused conv_q + conv_k (+ q maxpool), fp32 ----------------
__global__ __launch_bounds__(256)
void conv_qk_k(const float* __restrict__ wk, const float* __restrict__ bk,
               const float* __restrict__ wq, const float* __restrict__ bq,
               const float* __restrict__ x,
               float* __restrict__ kT, float* __restrict__ qT)
{
    __shared__ float As[16][68];
    __shared__ float Bs[16][128];
    __shared__ float Ks[32][132];
    __shared__ float Qs[32][128];

    const int b    = blockIdx.z;
    const int col0 = blockIdx.x * 128;
    const float* Bb = x + (size_t)b * CCH * NSP;
    const int tid  = threadIdx.x;
    const int tcol = tid & 15;
    const int trow = tid >> 4;

    const int a_r = tid >> 2;
    const int a_k = (tid & 3) * 4;
    const float* wrow = (a_r < 32) ? (wk + a_r * CCH) : (wq + (a_r - 32) * CCH);

    float acc[4][8] = {};

    for (int k0 = 0; k0 < CCH; k0 += 16) {
        float4 av = *(const float4*)&wrow[k0 + a_k];
        As[a_k + 0][a_r] = av.x;
        As[a_k + 1][a_r] = av.y;
        As[a_k + 2][a_r] = av.z;
        As[a_k + 3][a_r] = av.w;
#pragma unroll
        for (int i = 0; i < 2; i++) {
            int idx = tid + i * 256;
            int br = idx >> 5, bc = (idx & 31) * 4;
            *(float4*)&Bs[br][bc] = *(const float4*)&Bb[(size_t)(k0 + br) * NSP + col0 + bc];
        }
        __syncthreads();
#pragma unroll
        for (int kk = 0; kk < 16; kk++) {
            float ar[4], br[8];
            *(float4*)&ar[0] = *(const float4*)&As[kk][trow * 4];
            *(float4*)&br[0] = *(const float4*)&Bs[kk][tcol * 8 + 0];
            *(float4*)&br[4] = *(const float4*)&Bs[kk][tcol * 8 + 4];
#pragma unroll
            for (int i = 0; i < 4; i++)
#pragma unroll
                for (int j = 0; j < 8; j++) acc[i][j] += ar[i] * br[j];
        }
        __syncthreads();
    }

#pragma unroll
    for (int i = 0; i < 4; i++) {
        int r2 = trow * 4 + i;
        float bb = (r2 < 32) ? bk[r2] : bq[r2 - 32];
        if (r2 < 32) {
#pragma unroll
            for (int j = 0; j < 8; j++) Ks[r2][tcol * 8 + j] = acc[i][j] + bb;
        } else {
#pragma unroll
            for (int j = 0; j < 8; j++) Qs[r2 - 32][tcol * 8 + j] = acc[i][j] + bb;
        }
    }
    __syncthreads();

    float* kTb = kT + (size_t)b * NSP * CSP;
#pragma unroll
    for (int i = 0; i < 4; i++) {
        int idx = tid + i * 256;
        int mm = idx >> 3, cq = (idx & 7) * 4;
        float4 o;
        o.x = Ks[cq + 0][mm];
        o.y = Ks[cq + 1][mm];
        o.z = Ks[cq + 2][mm];
        o.w = Ks[cq + 3][mm];
        *(float4*)&kTb[(size_t)(col0 + mm) * CSP + cq] = o;
    }

    float* qTb = qT + (size_t)b * CSP * NPOOL;
    const int hp = col0 >> 7;
#pragma unroll
    for (int i = 0; i < 4; i++) {
        int idx = tid + i * 256;
        int cs = idx >> 5, wp = idx & 31;
        float v = fmaxf(fmaxf(Qs[cs][2 * wp], Qs[cs][2 * wp + 1]),
                        fmaxf(Qs[cs][64 + 2 * wp], Qs[cs][64 + 2 * wp + 1]));
        qTb[cs * NPOOL + hp * 32 + wp] = v;
    }
}

// ================= tf32 mma GEMM template =================
// C(M,N) = A(M,K, row-major K-contig) @ B(K,N, row-major N-contig).
// B transposed on load. Values RN-rounded to tf32 at smem store.
// Block 128x128, 8 warps of 64x32, KT=16.
// EPI 0: fp32 store (+bias if non-null), C batched (B,M,N)
// EPI 1: 2x2 maxpool epilogue -> C (B, M, N/4), bias added
// EPI 2: exp -> bf16 store to Ch (B, M, N) + column partials to part
template<int EPI, bool ABATCH>
__global__ __launch_bounds__(256)
void mma_gemm_k(const float* __restrict__ A,
                const float* __restrict__ B,
                const float* __restrict__ bias,
                float* __restrict__ C,
                __nv_bfloat16* __restrict__ Ch,
                float* __restrict__ part,
                int M, int N, int K)
{
    __shared__ float sA[128 * 20];
    __shared__ float sB[128 * 20];
    __shared__ float sX[(EPI == 1) ? 32 * 132 : ((EPI == 2) ? 16 * 132 : 1)];

    const int b  = blockIdx.z;
    const int r0 = blockIdx.y * 128;   // M offset
    const int n0 = blockIdx.x * 128;   // N offset
    const float* Ab = ABATCH ? (A + (size_t)b * M * K) : A;
    const float* Bb = B + (size_t)b * K * N;

    const int tid  = threadIdx.x;
    const int lane = tid & 31;
    const int wid  = tid >> 5;
    const int wr   = wid >> 2;         // 0..1 (M)
    const int wc   = wid & 3;          // 0..3 (N)
    const int g    = lane >> 2;        // 0..7
    const int tk   = lane & 3;         // 0..3

    float cf[4][4][4] = {};

    for (int k0 = 0; k0 < K; k0 += 16) {
        // A tile: 128 rows x 16 k
#pragma unroll
        for (int u = 0; u < 2; u++) {
            int idx = tid + u * 256;
            int r = idx >> 2, kq = (idx & 3) * 4;
            float4 v = *(const float4*)&Ab[(size_t)(r0 + r) * K + k0 + kq];
            v.x = tf32_rn(v.x); v.y = tf32_rn(v.y);
            v.z = tf32_rn(v.z); v.w = tf32_rn(v.w);
            *(float4*)&sA[r * 20 + kq] = v;
        }
        // B tile: 16 k x 128 n, transposed into sB[n][k]
#pragma unroll
        for (int u = 0; u < 2; u++) {
            int idx = tid + u * 256;
            int kr = idx >> 5, nc = (idx & 31) * 4;
            float4 v = *(const float4*)&Bb[(size_t)(k0 + kr) * N + n0 + nc];
            sB[(nc + 0) * 20 + kr] = tf32_rn(v.x);
            sB[(nc + 1) * 20 + kr] = tf32_rn(v.y);
            sB[(nc + 2) * 20 + kr] = tf32_rn(v.z);
            sB[(nc + 3) * 20 + kr] = tf32_rn(v.w);
        }
        __syncthreads();

#pragma unroll
        for (int ks = 0; ks < 2; ks++) {
            const int ko = ks * 8;
            uint32_t a[4][4], bf[4][2];
#pragma unroll
            for (int i = 0; i < 4; i++) {
                const int ra = (wr * 64 + i * 16 + g) * 20 + ko + tk;
                a[i][0] = __float_as_uint(sA[ra]);
                a[i][1] = __float_as_uint(sA[ra + 8 * 20]);
                a[i][2] = __float_as_uint(sA[ra + 4]);
                a[i][3] = __float_as_uint(sA[ra + 8 * 20 + 4]);
            }
#pragma unroll
            for (int j = 0; j < 4; j++) {
                const int rb = (wc * 32 + j * 8 + g) * 20 + ko + tk;
                bf[j][0] = __float_as_uint(sB[rb]);
                bf[j][1] = __float_as_uint(sB[rb + 4]);
            }
#pragma unroll
            for (int i = 0; i < 4; i++)
#pragma unroll
                for (int j = 0; j < 4; j++)
                    asm volatile(
                        "mma.sync.aligned.m16n8k8.row.col.f32.tf32.tf32.f32 "
                        "{%0,%1,%2,%3}, {%4,%5,%6,%7}, {%8,%9}, {%0,%1,%2,%3};"
                        : "+f"(cf[i][j][0]), "+f"(cf[i][j][1]),
                          "+f"(cf[i][j][2]), "+f"(cf[i][j][3])
                        : "r"(a[i][0]), "r"(a[i][1]), "r"(a[i][2]), "r"(a[i][3]),
                          "r"(bf[j][0]), "r"(bf[j][1]));
        }
        __syncthreads();
    }

    if (EPI == 0) {
        float* Cb = C + (size_t)b * M * N;
#pragma unroll
        for (int i = 0; i < 4; i++) {
#pragma unroll
            for (int half = 0; half < 2; half++) {
                const int r = r0 + wr * 64 + i * 16 + g + half * 8;
                const float bv = (bias != nullptr) ? bias[r] : 0.f;
                const size_t ro = (size_t)r * N;
#pragma unroll
                for (int j = 0; j < 4; j++) {
                    const int c = n0 + wc * 32 + j * 8 + 2 * tk;
                    float2 o;
                    o.x = cf[i][j][half * 2 + 0] + bv;
                    o.y = cf[i][j][half * 2 + 1] + bv;
                    *(float2*)&Cb[ro + c] = o;
                }
            }
        }
    }

    if (EPI == 1) {
        // pooled output: (B, M, N/4); tile covers 2 image rows of 64 pixels
        float* Cp = C + (size_t)b * M * (N / 4);
        const int pcb = n0 >> 2;   // pooled col base
#pragma unroll 1
        for (int s = 0; s < 4; s++) {
            if (wr == (s >> 1)) {
#pragma unroll
                for (int ii = 0; ii < 2; ii++) {
                    const int i = (s & 1) * 2 + ii;
#pragma unroll
                    for (int half = 0; half < 2; half++) {
                        const int lr = ii * 16 + half * 8 + g;
#pragma unroll
                        for (int j = 0; j < 4; j++) {
                            const int col = wc * 32 + j * 8 + 2 * tk;
                            sX[lr * 132 + col]     = cf[i][j][half * 2 + 0];
                            sX[lr * 132 + col + 1] = cf[i][j][half * 2 + 1];
                        }
                    }
                }
            }
            __syncthreads();
#pragma unroll
            for (int u = 0; u < 4; u++) {
                int po = tid + u * 256;
                int rr = po >> 5, pc = po & 31;
                float v = fmaxf(fmaxf(sX[rr * 132 + 2 * pc], sX[rr * 132 + 2 * pc + 1]),
                                fmaxf(sX[rr * 132 + 64 + 2 * pc], sX[rr * 132 + 64 + 2 * pc + 1]));
                const int r = r0 + s * 32 + rr;
                Cp[(size_t)r * (N / 4) + pcb + pc] = v + bias[r];
            }
            __syncthreads();
        }
    }

    if (EPI == 2) {
        __nv_bfloat16* Cb = Ch + (size_t)b * M * N;
        float colsum[4][2] = {};
#pragma unroll
        for (int i = 0; i < 4; i++) {
#pragma unroll
            for (int half = 0; half < 2; half++) {
                const int r = r0 + wr * 64 + i * 16 + g + half * 8;
                const size_t ro = (size_t)r * N;
#pragma unroll
                for (int j = 0; j < 4; j++) {
                    const int c = n0 + wc * 32 + j * 8 + 2 * tk;
                    float e0 = __expf(cf[i][j][half * 2 + 0]);
                    float e1 = __expf(cf[i][j][half * 2 + 1]);
                    colsum[j][0] += e0;
                    colsum[j][1] += e1;
                    *(__nv_bfloat162*)&Cb[ro + c] =
                        __floats2bfloat162_rn(e0, e1);
                }
            }
        }
        // reduce column sums: sX[16][132]
#pragma unroll
        for (int j = 0; j < 4; j++) {
            const int col = wc * 32 + j * 8 + 2 * tk;
            sX[(wr * 8 + g) * 132 + col]     = colsum[j][0];
            sX[(wr * 8 + g) * 132 + col + 1] = colsum[j][1];
        }
        __syncthreads();
        if (tid < 128) {
            float t = 0.f;
#pragma unroll
            for (int k = 0; k < 16; k++) t += sX[k * 132 + tid];
            part[((size_t)b * 32 + blockIdx.y) * N + n0 + tid] = t;
        }
    }
}

// ---------------- denominator: sum 32 partials per (b, np) ----------------
__global__ void invden_k(const float* __restrict__ part, float* __restrict__ invden)
{
    int idx = blockIdx.x * 256 + threadIdx.x;
    int b  = idx >> 10;
    int np = idx & 1023;
    const float* p = part + (size_t)b * 32 * NPOOL + np;
    float s = 0.f;
#pragma unroll
    for (int i = 0; i < 32; i++) s += p[(size_t)i * NPOOL];
    invden[idx] = 1.f / s;
}

// ---------------- v'' = bf16(v' / denom[np]) ----------------
__global__ void scale_v_k(const float* __restrict__ vpr,
                          const float* __restrict__ invden,
                          __nv_bfloat16* __restrict__ vppb)
{
    int idx = blockIdx.x * 256 + threadIdx.x;
    int np = idx & 1023;
    int b  = idx >> 18;
    vppb[idx] = __float2bfloat16_rn(vpr[idx] * invden[b * NPOOL + np]);
}

// ---------------- final GEMM: bf16 mma m16n8k16 ----------------
// out[c][m] = gamma*( sum_np v''[c][np]*p[m][np] + bo[c] ) + x[c][m]
__global__ __launch_bounds__(256)
void final_bf16_k(const __nv_bfloat16* __restrict__ vpp,
                  const __nv_bfloat16* __restrict__ pm,
                  const float* __restrict__ bo,
                  const float* __restrict__ gamma,
                  const float* __restrict__ xres,
                  float* __restrict__ out)
{
    __shared__ uint32_t uA[128 * 20];
    __shared__ uint32_t uB[128 * 20];

    const int tid  = threadIdx.x;
    const int lane = tid & 31;
    const int wid  = tid >> 5;
    const int b  = blockIdx.z;
    const int c0 = blockIdx.y * 128;
    const int m0 = blockIdx.x * 128;
    const int wr = wid >> 2;
    const int wc = wid & 3;
    const int g  = lane >> 2;
    const int tk = lane & 3;

    const __nv_bfloat16* Ab = vpp + ((size_t)b * CCH + c0) * NPOOL;
    const __nv_bfloat16* Bb = pm  + ((size_t)b * NSP + m0) * NPOOL;

    float cf[4][4][4] = {};

    for (int kt = 0; kt < NPOOL / 32; kt++) {
        const int kb = kt * 32;
#pragma unroll
        for (int u = 0; u < 2; u++) {
            int idx = tid + u * 256;
            int r = idx >> 2, cq = idx & 3;
            uint4 va = *(const uint4*)&Ab[(size_t)r * NPOOL + kb + cq * 8];
            *(uint4*)&uA[r * 20 + cq * 4] = va;
            uint4 vb = *(const uint4*)&Bb[(size_t)r * NPOOL + kb + cq * 8];
            *(uint4*)&uB[r * 20 + cq * 4] = vb;
        }
        __syncthreads();

#pragma unroll
        for (int ks = 0; ks < 2; ks++) {
            const int ko = ks * 8;
            uint32_t a[4][4], bf[4][2];
#pragma unroll
            for (int i = 0; i < 4; i++) {
                const int ra = (wr * 64 + i * 16 + g) * 20 + ko + tk;
                a[i][0] = uA[ra];
                a[i][1] = uA[ra + 8 * 20];
                a[i][2] = uA[ra + 4];
                a[i][3] = uA[ra + 8 * 20 + 4];
            }
#pragma unroll
            for (int j = 0; j < 4; j++) {
                const int rb = (wc * 32 + j * 8 + g) * 20 + ko + tk;
                bf[j][0] = uB[rb];
                bf[j][1] = uB[rb + 4];
            }
#pragma unroll
            for (int i = 0; i < 4; i++)
#pragma unroll
                for (int j = 0; j < 4; j++)
                    asm volatile(
                        "mma.sync.aligned.m16n8k16.row.col.f32.bf16.bf16.f32 "
                        "{%0,%1,%2,%3}, {%4,%5,%6,%7}, {%8,%9}, {%0,%1,%2,%3};"
                        : "+f"(cf[i][j][0]), "+f"(cf[i][j][1]),
                          "+f"(cf[i][j][2]), "+f"(cf[i][j][3])
                        : "r"(a[i][0]), "r"(a[i][1]), "r"(a[i][2]), "r"(a[i][3]),
                          "r"(bf[j][0]), "r"(bf[j][1]));
        }
        __syncthreads();
    }

    const float gm = gamma[0];
#pragma unroll
    for (int i = 0; i < 4; i++) {
#pragma unroll
        for (int half = 0; half < 2; half++) {
            const int c = c0 + wr * 64 + i * 16 + g + half * 8;
            const float bc = bo[c];
            const size_t ro = ((size_t)b * CCH + c) * NSP;
#pragma unroll
            for (int j = 0; j < 4; j++) {
                const int m = m0 + wc * 32 + j * 8 + 2 * tk;
                float2 xr = *(const float2*)&xres[ro + m];
                float2 o;
                o.x = gm * (cf[i][j][half * 2 + 0] + bc) + xr.x;
                o.y = gm * (cf[i][j][half * 2 + 1] + bc) + xr.y;
                *(float2*)&out[ro + m] = o;
            }
        }
    }
}

// ---------------- launch ----------------
extern "C" void kernel_launch(void* const* d_in, const int* in_sizes, int n_in,
                              void* d_out, int out_size)
{
    const float* x     = (const float*)d_in[0];
    const float* wq    = (const float*)d_in[1];
    const float* bq    = (const float*)d_in[2];
    const float* wk    = (const float*)d_in[3];
    const float* bk    = (const float*)d_in[4];
    const float* wv    = (const float*)d_in[5];
    const float* bv    = (const float*)d_in[6];
    const float* wo    = (const float*)d_in[7];
    const float* bo    = (const float*)d_in[8];
    const float* gamma = (const float*)d_in[9];
    float* out = (float*)d_out;

    float *pkT, *pqT, *pvp, *pvpr, *ppart, *pinv;
    __nv_bfloat16 *pattnh, *pvppb;
    cudaGetSymbolAddress((void**)&pkT,    g_kT);
    cudaGetSymbolAddress((void**)&pqT,    g_qT);
    cudaGetSymbolAddress((void**)&pvp,    g_vpool);
    cudaGetSymbolAddress((void**)&pvpr,   g_vprime);
    cudaGetSymbolAddress((void**)&ppart,  g_part);
    cudaGetSymbolAddress((void**)&pinv,   g_invden);
    cudaGetSymbolAddress((void**)&pattnh, g_attnh);
    cudaGetSymbolAddress((void**)&pvppb,  g_vppb);

    static cudaStream_t s1 = nullptr;
    static cudaEvent_t evFork = nullptr, evJoin = nullptr;
    if (s1 == nullptr) {
        cudaStreamCreateWithFlags(&s1, cudaStreamNonBlocking);
        cudaEventCreateWithFlags(&evFork, cudaEventDisableTiming);
        cudaEventCreateWithFlags(&evJoin, cudaEventDisableTiming);
    }

    cudaEventRecord(evFork, 0);
    cudaStreamWaitEvent(s1, evFork, 0);

    // --- s1: V branch (tf32 mma) ---
    {   // vpool = maxpool(wv @ x + bv)
        dim3 g(NSP / 128, CCH / 128, BATCH);
        mma_gemm_k<1, false><<<g, 256, 0, s1>>>(wv, x, bv, pvp, nullptr, nullptr,
                                                CCH, NSP, CCH);
    }
    {   // v' = wo @ vpool (fp32 out; bo folded into final epilogue)
        dim3 g(NPOOL / 128, CCH / 128, BATCH);
        mma_gemm_k<0, false><<<g, 256, 0, s1>>>(wo, pvp, nullptr, pvpr, nullptr, nullptr,
                                                CCH, NPOOL, CCH);
    }
    cudaEventRecord(evJoin, s1);

    // --- main: conv_qk -> energy(tf32 mma, exp -> bf16 + partials) -> invden ---
    {
        dim3 g(NSP / 128, 1, BATCH);
        conv_qk_k<<<g, 256>>>(wk, bk, wq, bq, x, pkT, pqT);
    }
    {   // p = bf16(exp(kT @ qT)), partials
        dim3 g(NPOOL / 128, NSP / 128, BATCH);
        mma_gemm_k<2, true><<<g, 256>>>(pkT, pqT, nullptr, nullptr, pattnh, ppart,
                                        NSP, NPOOL, CSP);
    }
    invden_k<<<BATCH * NPOOL / 256, 256>>>(ppart, pinv);

    // join; fold denom into v'' (bf16); bf16 tensor-core final
    cudaStreamWaitEvent(0, evJoin, 0);
    scale_v_k<<<BATCH * CCH * NPOOL / 256, 256>>>(pvpr, pinv, pvppb);
    {
        dim3 g(NSP / 128, CCH / 128, BATCH);
        final_bf16_k<<<g, 256>>>(pvppb, pattnh, bo, gamma, x, out);
    }
}

// round 7
// speedup vs baseline: 4.4027x; 1.0747x over previous
#include <cuda_runtime.h>
#include <cuda_bf16.h>
#include <math.h>
#include <stdint.h>

#define BATCH 16
#define CCH   256
#define NSP   4096   // 64*64
#define CSP   32     // C/8
#define NPOOL 1024   // 32*32

// ---------------- scratch ----------------
__device__ float g_kT[BATCH * NSP * CSP];                    //  8 MB tf32 (B, n, 32)
__device__ float g_qT[BATCH * NPOOL * CSP];                  //  2 MB tf32 (B, np, 32)
__device__ float g_vpool[BATCH * CCH * NPOOL];               // 16 MB
__device__ float g_vprime[BATCH * CCH * NPOOL];              // 16 MB
__device__ float g_part[BATCH * 32 * NPOOL];                 //  2 MB
__device__ float g_invden[BATCH * NPOOL];                    // 64 KB
__device__ __nv_bfloat16 g_attnh[(size_t)BATCH * NSP * NPOOL]; // 128 MB
__device__ __nv_bfloat16 g_vppb[BATCH * CCH * NPOOL];        //  8 MB

// ---------------- helpers ----------------
__device__ __forceinline__ float tf32_rn(float v) {
    uint32_t u;
    asm("cvt.rna.tf32.f32 %0, %1;" : "=r"(u) : "f"(v));
    return __uint_as_float(u);
}
__device__ __forceinline__ void mma_tf32(float* c, const uint32_t* a, const uint32_t* b) {
    asm volatile(
        "mma.sync.aligned.m16n8k8.row.col.f32.tf32.tf32.f32 "
        "{%0,%1,%2,%3}, {%4,%5,%6,%7}, {%8,%9}, {%0,%1,%2,%3};"
        : "+f"(c[0]), "+f"(c[1]), "+f"(c[2]), "+f"(c[3])
        : "r"(a[0]), "r"(a[1]), "r"(a[2]), "r"(a[3]), "r"(b[0]), "r"(b[1]));
}
__device__ __forceinline__ void mma_bf16(float* c, const uint32_t* a, const uint32_t* b) {
    asm volatile(
        "mma.sync.aligned.m16n8k16.row.col.f32.bf16.bf16.f32 "
        "{%0,%1,%2,%3}, {%4,%5,%6,%7}, {%8,%9}, {%0,%1,%2,%3};"
        : "+f"(c[0]), "+f"(c[1]), "+f"(c[2]), "+f"(c[3])
        : "r"(a[0]), "r"(a[1]), "r"(a[2]), "r"(a[3]), "r"(b[0]), "r"(b[1]));
}
__device__ __forceinline__ void cpa16(uint32_t dst, const void* src) {
    asm volatile("cp.async.cg.shared.global [%0], [%1], 16;" :: "r"(dst), "l"(src));
}

// ============ conv_qk via tf32 mma: kT (B,n,32) + pooled qT (B,np,32) ============
__global__ __launch_bounds__(256)
void conv_qk_mma(const float* __restrict__ wk, const float* __restrict__ bk,
                 const float* __restrict__ wq, const float* __restrict__ bq,
                 const float* __restrict__ x,
                 float* __restrict__ kT, float* __restrict__ qT)
{
    __shared__ union {
        struct { float sA[64 * 20]; float sB[128 * 20]; } ld;
        float sOut[64 * 132];
    } sh;

    const int b    = blockIdx.z;
    const int col0 = blockIdx.x * 128;
    const float* xb = x + (size_t)b * CCH * NSP;
    const int tid = threadIdx.x, lane = tid & 31, wid = tid >> 5;
    const int wr = wid >> 2, wc = wid & 3;   // m half (32), n quarter (32)
    const int g = lane >> 2, tk = lane & 3;

    float cf[2][4][4] = {};

    for (int k0 = 0; k0 < CCH; k0 += 16) {
        {   // A: 64 ch-rows x 16 k
            int r = tid >> 2, kq = (tid & 3) * 4;
            const float* wrow = (r < 32) ? (wk + r * CCH) : (wq + (r - 32) * CCH);
            float4 v = *(const float4*)&wrow[k0 + kq];
            v.x = tf32_rn(v.x); v.y = tf32_rn(v.y);
            v.z = tf32_rn(v.z); v.w = tf32_rn(v.w);
            *(float4*)&sh.ld.sA[r * 20 + kq] = v;
        }
#pragma unroll
        for (int u = 0; u < 2; u++) {   // B: 16k x 128n transposed
            int idx = tid + u * 256;
            int kr = idx >> 5, nc = (idx & 31) * 4;
            float4 v = *(const float4*)&xb[(size_t)(k0 + kr) * NSP + col0 + nc];
            sh.ld.sB[(nc + 0) * 20 + kr] = tf32_rn(v.x);
            sh.ld.sB[(nc + 1) * 20 + kr] = tf32_rn(v.y);
            sh.ld.sB[(nc + 2) * 20 + kr] = tf32_rn(v.z);
            sh.ld.sB[(nc + 3) * 20 + kr] = tf32_rn(v.w);
        }
        __syncthreads();
#pragma unroll
        for (int ks = 0; ks < 2; ks++) {
            const int ko = ks * 8;
            uint32_t a[2][4], bf[4][2];
#pragma unroll
            for (int i = 0; i < 2; i++) {
                const int ra = (wr * 32 + i * 16 + g) * 20 + ko + tk;
                a[i][0] = __float_as_uint(sh.ld.sA[ra]);
                a[i][1] = __float_as_uint(sh.ld.sA[ra + 8 * 20]);
                a[i][2] = __float_as_uint(sh.ld.sA[ra + 4]);
                a[i][3] = __float_as_uint(sh.ld.sA[ra + 8 * 20 + 4]);
            }
#pragma unroll
            for (int j = 0; j < 4; j++) {
                const int rb = (wc * 32 + j * 8 + g) * 20 + ko + tk;
                bf[j][0] = __float_as_uint(sh.ld.sB[rb]);
                bf[j][1] = __float_as_uint(sh.ld.sB[rb + 4]);
            }
#pragma unroll
            for (int i = 0; i < 2; i++)
#pragma unroll
                for (int j = 0; j < 4; j++) mma_tf32(cf[i][j], a[i], bf[j]);
        }
        __syncthreads();
    }

    // stage 64 x 128 results
#pragma unroll
    for (int i = 0; i < 2; i++)
#pragma unroll
        for (int half = 0; half < 2; half++) {
            const int r = wr * 32 + i * 16 + half * 8 + g;
#pragma unroll
            for (int j = 0; j < 4; j++) {
                const int c = wc * 32 + j * 8 + 2 * tk;
                sh.sOut[r * 132 + c]     = cf[i][j][half * 2 + 0];
                sh.sOut[r * 132 + c + 1] = cf[i][j][half * 2 + 1];
            }
        }
    __syncthreads();

    // kT: (col0+nn, cs) tf32
    float* kTb = kT + (size_t)b * NSP * CSP;
#pragma unroll
    for (int u = 0; u < 4; u++) {
        int idx = tid + u * 256;
        int nn = idx >> 3, csq = (idx & 7) * 4;
        float4 o;
        o.x = tf32_rn(sh.sOut[(csq + 0) * 132 + nn] + bk[csq + 0]);
        o.y = tf32_rn(sh.sOut[(csq + 1) * 132 + nn] + bk[csq + 1]);
        o.z = tf32_rn(sh.sOut[(csq + 2) * 132 + nn] + bk[csq + 2]);
        o.w = tf32_rn(sh.sOut[(csq + 3) * 132 + nn] + bk[csq + 3]);
        *(float4*)&kTb[(size_t)(col0 + nn) * CSP + csq] = o;
    }

    // qT: pooled (hp*32+wp, cs) tf32; tile covers image rows 2hp, 2hp+1
    float* qTb = qT + (size_t)b * NPOOL * CSP;
    const int hp = col0 >> 7;
    {
        int wp = tid >> 3, csq = (tid & 7) * 4;
        float4 o;
        float* oc = &o.x;
#pragma unroll
        for (int t = 0; t < 4; t++) {
            const int cs = csq + t;
            const float* r = &sh.sOut[(32 + cs) * 132];
            float v = fmaxf(fmaxf(r[2 * wp], r[2 * wp + 1]),
                            fmaxf(r[64 + 2 * wp], r[64 + 2 * wp + 1]));
            oc[t] = tf32_rn(v + bq[cs]);
        }
        *(float4*)&qTb[(size_t)(hp * 32 + wp) * CSP + csq] = o;
    }
}

// ============ energy via tf32 mma (K=32 single-shot) + exp -> bf16 + partials ====
__global__ __launch_bounds__(256)
void energy_mma(const float* __restrict__ kTg, const float* __restrict__ qTg,
                __nv_bfloat16* __restrict__ attnh, float* __restrict__ part)
{
    __shared__ float sA[128 * 36];
    __shared__ float sB[128 * 36];
    __shared__ float sX[16 * 132];

    const int b  = blockIdx.z;
    const int m0 = blockIdx.y * 128;   // keys (4096)
    const int n0 = blockIdx.x * 128;   // queries np (1024)
    const float* Ab = kTg + ((size_t)b * NSP + m0) * CSP;
    const float* Bb = qTg + ((size_t)b * NPOOL + n0) * CSP;

    const int tid = threadIdx.x, lane = tid & 31, wid = tid >> 5;
    const int wr = wid >> 2, wc = wid & 3;
    const int g = lane >> 2, tk = lane & 3;

#pragma unroll
    for (int u = 0; u < 4; u++) {
        int idx = tid + u * 256;
        int r = idx >> 3, kq = (idx & 7) * 4;
        *(float4*)&sA[r * 36 + kq] = *(const float4*)&Ab[(size_t)r * CSP + kq];
        *(float4*)&sB[r * 36 + kq] = *(const float4*)&Bb[(size_t)r * CSP + kq];
    }
    __syncthreads();

    float cf[4][4][4] = {};
#pragma unroll
    for (int ks = 0; ks < 4; ks++) {
        const int ko = ks * 8;
        uint32_t a[4][4], bf[4][2];
#pragma unroll
        for (int i = 0; i < 4; i++) {
            const int ra = (wr * 64 + i * 16 + g) * 36 + ko + tk;
            a[i][0] = __float_as_uint(sA[ra]);
            a[i][1] = __float_as_uint(sA[ra + 8 * 36]);
            a[i][2] = __float_as_uint(sA[ra + 4]);
            a[i][3] = __float_as_uint(sA[ra + 8 * 36 + 4]);
        }
#pragma unroll
        for (int j = 0; j < 4; j++) {
            const int rb = (wc * 32 + j * 8 + g) * 36 + ko + tk;
            bf[j][0] = __float_as_uint(sB[rb]);
            bf[j][1] = __float_as_uint(sB[rb + 4]);
        }
#pragma unroll
        for (int i = 0; i < 4; i++)
#pragma unroll
            for (int j = 0; j < 4; j++) mma_tf32(cf[i][j], a[i], bf[j]);
    }

    __nv_bfloat16* Cb = attnh + (size_t)b * NSP * NPOOL;
    float colsum[4][2] = {};
#pragma unroll
    for (int i = 0; i < 4; i++) {
#pragma unroll
        for (int half = 0; half < 2; half++) {
            const int r = m0 + wr * 64 + i * 16 + g + half * 8;
            const size_t ro = (size_t)r * NPOOL;
#pragma unroll
            for (int j = 0; j < 4; j++) {
                const int c = n0 + wc * 32 + j * 8 + 2 * tk;
                float e0 = __expf(cf[i][j][half * 2 + 0]);
                float e1 = __expf(cf[i][j][half * 2 + 1]);
                colsum[j][0] += e0;
                colsum[j][1] += e1;
                *(__nv_bfloat162*)&Cb[ro + c] = __floats2bfloat162_rn(e0, e1);
            }
        }
    }
#pragma unroll
    for (int j = 0; j < 4; j++) {
        const int col = wc * 32 + j * 8 + 2 * tk;
        sX[(wr * 8 + g) * 132 + col]     = colsum[j][0];
        sX[(wr * 8 + g) * 132 + col + 1] = colsum[j][1];
    }
    __syncthreads();
    if (tid < 128) {
        float t = 0.f;
#pragma unroll
        for (int k = 0; k < 16; k++) t += sX[k * 132 + tid];
        part[((size_t)b * 32 + blockIdx.y) * NPOOL + n0 + tid] = t;
    }
}

// ================= tf32 mma GEMM (V branch; from R6) =================
// EPI 0: fp32 store (+bias); EPI 1: 2x2 maxpool -> (B, M, N/4)
template<int EPI>
__global__ __launch_bounds__(256)
void mma_gemm_k(const float* __restrict__ A,
                const float* __restrict__ B,
                const float* __restrict__ bias,
                float* __restrict__ C,
                int M, int N, int K)
{
    __shared__ float sA[128 * 20];
    __shared__ float sB[128 * 20];
    __shared__ float sX[(EPI == 1) ? 32 * 132 : 1];

    const int b  = blockIdx.z;
    const int r0 = blockIdx.y * 128;
    const int n0 = blockIdx.x * 128;
    const float* Ab = A;
    const float* Bb = B + (size_t)b * K * N;

    const int tid = threadIdx.x, lane = tid & 31, wid = tid >> 5;
    const int wr = wid >> 2, wc = wid & 3;
    const int g = lane >> 2, tk = lane & 3;

    float cf[4][4][4] = {};

    for (int k0 = 0; k0 < K; k0 += 16) {
#pragma unroll
        for (int u = 0; u < 2; u++) {
            int idx = tid + u * 256;
            int r = idx >> 2, kq = (idx & 3) * 4;
            float4 v = *(const float4*)&Ab[(size_t)(r0 + r) * K + k0 + kq];
            v.x = tf32_rn(v.x); v.y = tf32_rn(v.y);
            v.z = tf32_rn(v.z); v.w = tf32_rn(v.w);
            *(float4*)&sA[r * 20 + kq] = v;
        }
#pragma unroll
        for (int u = 0; u < 2; u++) {
            int idx = tid + u * 256;
            int kr = idx >> 5, nc = (idx & 31) * 4;
            float4 v = *(const float4*)&Bb[(size_t)(k0 + kr) * N + n0 + nc];
            sB[(nc + 0) * 20 + kr] = tf32_rn(v.x);
            sB[(nc + 1) * 20 + kr] = tf32_rn(v.y);
            sB[(nc + 2) * 20 + kr] = tf32_rn(v.z);
            sB[(nc + 3) * 20 + kr] = tf32_rn(v.w);
        }
        __syncthreads();
#pragma unroll
        for (int ks = 0; ks < 2; ks++) {
            const int ko = ks * 8;
            uint32_t a[4][4], bf[4][2];
#pragma unroll
            for (int i = 0; i < 4; i++) {
                const int ra = (wr * 64 + i * 16 + g) * 20 + ko + tk;
                a[i][0] = __float_as_uint(sA[ra]);
                a[i][1] = __float_as_uint(sA[ra + 8 * 20]);
                a[i][2] = __float_as_uint(sA[ra + 4]);
                a[i][3] = __float_as_uint(sA[ra + 8 * 20 + 4]);
            }
#pragma unroll
            for (int j = 0; j < 4; j++) {
                const int rb = (wc * 32 + j * 8 + g) * 20 + ko + tk;
                bf[j][0] = __float_as_uint(sB[rb]);
                bf[j][1] = __float_as_uint(sB[rb + 4]);
            }
#pragma unroll
            for (int i = 0; i < 4; i++)
#pragma unroll
                for (int j = 0; j < 4; j++) mma_tf32(cf[i][j], a[i], bf[j]);
        }
        __syncthreads();
    }

    if (EPI == 0) {
        float* Cb = C + (size_t)b * M * N;
#pragma unroll
        for (int i = 0; i < 4; i++)
#pragma unroll
            for (int half = 0; half < 2; half++) {
                const int r = r0 + wr * 64 + i * 16 + g + half * 8;
                const float bv = (bias != nullptr) ? bias[r] : 0.f;
                const size_t ro = (size_t)r * N;
#pragma unroll
                for (int j = 0; j < 4; j++) {
                    const int c = n0 + wc * 32 + j * 8 + 2 * tk;
                    float2 o;
                    o.x = cf[i][j][half * 2 + 0] + bv;
                    o.y = cf[i][j][half * 2 + 1] + bv;
                    *(float2*)&C[(size_t)b * M * N + ro + c] = o;
                }
            }
    }

    if (EPI == 1) {
        float* Cp = C + (size_t)b * M * (N / 4);
        const int pcb = n0 >> 2;
#pragma unroll 1
        for (int s = 0; s < 4; s++) {
            if (wr == (s >> 1)) {
#pragma unroll
                for (int ii = 0; ii < 2; ii++) {
                    const int i = (s & 1) * 2 + ii;
#pragma unroll
                    for (int half = 0; half < 2; half++) {
                        const int lr = ii * 16 + half * 8 + g;
#pragma unroll
                        for (int j = 0; j < 4; j++) {
                            const int col = wc * 32 + j * 8 + 2 * tk;
                            sX[lr * 132 + col]     = cf[i][j][half * 2 + 0];
                            sX[lr * 132 + col + 1] = cf[i][j][half * 2 + 1];
                        }
                    }
                }
            }
            __syncthreads();
#pragma unroll
            for (int u = 0; u < 4; u++) {
                int po = tid + u * 256;
                int rr = po >> 5, pc = po & 31;
                float v = fmaxf(fmaxf(sX[rr * 132 + 2 * pc], sX[rr * 132 + 2 * pc + 1]),
                                fmaxf(sX[rr * 132 + 64 + 2 * pc], sX[rr * 132 + 64 + 2 * pc + 1]));
                const int r = r0 + s * 32 + rr;
                Cp[(size_t)r * (N / 4) + pcb + pc] = v + bias[r];
            }
            __syncthreads();
        }
    }
}

// ---------------- denominator + v'' ----------------
__global__ void invden_k(const float* __restrict__ part, float* __restrict__ invden)
{
    int idx = blockIdx.x * 256 + threadIdx.x;
    int b  = idx >> 10;
    int np = idx & 1023;
    const float* p = part + (size_t)b * 32 * NPOOL + np;
    float s = 0.f;
#pragma unroll
    for (int i = 0; i < 32; i++) s += p[(size_t)i * NPOOL];
    invden[idx] = 1.f / s;
}

__global__ void scale_v_k(const float* __restrict__ vpr,
                          const float* __restrict__ invden,
                          __nv_bfloat16* __restrict__ vppb)
{
    int idx = blockIdx.x * 256 + threadIdx.x;
    int np = idx & 1023;
    int b  = idx >> 18;
    vppb[idx] = __float2bfloat16_rn(vpr[idx] * invden[b * NPOOL + np]);
}

// ============ final bf16 mma: full-C tile 256x128, cp.async double buffer =====
#define FSTRIDE 12
__global__ __launch_bounds__(256)
void final2_k(const __nv_bfloat16* __restrict__ vpp,
              const __nv_bfloat16* __restrict__ pm,
              const float* __restrict__ bo,
              const float* __restrict__ gamma,
              const float* __restrict__ xres,
              float* __restrict__ out)
{
    __shared__ uint32_t uA[2][256 * FSTRIDE];
    __shared__ uint32_t uB[2][128 * FSTRIDE];

    const int tid = threadIdx.x, lane = tid & 31, wid = tid >> 5;
    const int b  = blockIdx.z;
    const int m0 = blockIdx.x * 128;
    const int wr = wid >> 1;           // 0..3 : c 64-quarter
    const int wc = wid & 1;            // 0..1 : m 64-half
    const int g = lane >> 2, tk = lane & 3;

    const __nv_bfloat16* Ab = vpp + (size_t)b * CCH * NPOOL;
    const __nv_bfloat16* Bb = pm + ((size_t)b * NSP + m0) * NPOOL;

    const int ar = tid >> 1, acq = tid & 1;      // A: 2 chunks/thread
    const int br = tid >> 1;                     // B: 1 chunk/thread (tid<256 covers 128r x 2)
    uint32_t aDst0 = (uint32_t)__cvta_generic_to_shared(&uA[0][ar * FSTRIDE + acq * 4]);
    uint32_t aDst1 = (uint32_t)__cvta_generic_to_shared(&uA[0][(ar + 128) * FSTRIDE + acq * 4]);
    uint32_t bDst  = (uint32_t)__cvta_generic_to_shared(&uB[0][br * FSTRIDE + (tid & 1) * 4]);
    const uint32_t bufStepA = 256 * FSTRIDE * 4;
    const uint32_t bufStepB = 128 * FSTRIDE * 4;

    float cf[4][8][4] = {};

    auto issue = [&](int kt, int s) {
        const int kb = kt * 16;   // bf16 k offset
        cpa16(aDst0 + s * bufStepA, &Ab[(size_t)ar * NPOOL + kb + acq * 8]);
        cpa16(aDst1 + s * bufStepA, &Ab[(size_t)(ar + 128) * NPOOL + kb + acq * 8]);
        cpa16(bDst + s * bufStepB, &Bb[(size_t)br * NPOOL + kb + (tid & 1) * 8]);
        asm volatile("cp.async.commit_group;");
    };

    issue(0, 0);
    for (int kt = 0; kt < NPOOL / 16; kt++) {
        const int cur = kt & 1;
        if (kt < NPOOL / 16 - 1) {
            issue(kt + 1, cur ^ 1);
            asm volatile("cp.async.wait_group 1;");
        } else {
            asm volatile("cp.async.wait_group 0;");
        }
        __syncthreads();

        uint32_t a[4][4], bf[8][2];
#pragma unroll
        for (int i = 0; i < 4; i++) {
            const int ra = (wr * 64 + i * 16 + g) * FSTRIDE + tk;
            a[i][0] = uA[cur][ra];
            a[i][1] = uA[cur][ra + 8 * FSTRIDE];
            a[i][2] = uA[cur][ra + 4];
            a[i][3] = uA[cur][ra + 8 * FSTRIDE + 4];
        }
#pragma unroll
        for (int j = 0; j < 8; j++) {
            const int rb = (wc * 64 + j * 8 + g) * FSTRIDE + tk;
            bf[j][0] = uB[cur][rb];
            bf[j][1] = uB[cur][rb + 4];
        }
#pragma unroll
        for (int i = 0; i < 4; i++)
#pragma unroll
            for (int j = 0; j < 8; j++) mma_bf16(cf[i][j], a[i], bf[j]);
        __syncthreads();
    }

    const float gm = gamma[0];
#pragma unroll
    for (int i = 0; i < 4; i++) {
#pragma unroll
        for (int half = 0; half < 2; half++) {
            const int c = wr * 64 + i * 16 + g + half * 8;
            const float bc = bo[c];
            const size_t ro = ((size_t)b * CCH + c) * NSP;
#pragma unroll
            for (int j = 0; j < 8; j++) {
                const int m = m0 + wc * 64 + j * 8 + 2 * tk;
                float2 xr = *(const float2*)&xres[ro + m];
                float2 o;
                o.x = gm * (cf[i][j][half * 2 + 0] + bc) + xr.x;
                o.y = gm * (cf[i][j][half * 2 + 1] + bc) + xr.y;
                *(float2*)&out[ro + m] = o;
            }
        }
    }
}

// ---------------- launch ----------------
extern "C" void kernel_launch(void* const* d_in, const int* in_sizes, int n_in,
                              void* d_out, int out_size)
{
    const float* x     = (const float*)d_in[0];
    const float* wq    = (const float*)d_in[1];
    const float* bq    = (const float*)d_in[2];
    const float* wk    = (const float*)d_in[3];
    const float* bk    = (const float*)d_in[4];
    const float* wv    = (const float*)d_in[5];
    const float* bv    = (const float*)d_in[6];
    const float* wo    = (const float*)d_in[7];
    const float* bo    = (const float*)d_in[8];
    const float* gamma = (const float*)d_in[9];
    float* out = (float*)d_out;

    float *pkT, *pqT, *pvp, *pvpr, *ppart, *pinv;
    __nv_bfloat16 *pattnh, *pvppb;
    cudaGetSymbolAddress((void**)&pkT,    g_kT);
    cudaGetSymbolAddress((void**)&pqT,    g_qT);
    cudaGetSymbolAddress((void**)&pvp,    g_vpool);
    cudaGetSymbolAddress((void**)&pvpr,   g_vprime);
    cudaGetSymbolAddress((void**)&ppart,  g_part);
    cudaGetSymbolAddress((void**)&pinv,   g_invden);
    cudaGetSymbolAddress((void**)&pattnh, g_attnh);
    cudaGetSymbolAddress((void**)&pvppb,  g_vppb);

    static cudaStream_t s1 = nullptr;
    static cudaEvent_t evFork = nullptr, evJoin = nullptr;
    if (s1 == nullptr) {
        cudaStreamCreateWithFlags(&s1, cudaStreamNonBlocking);
        cudaEventCreateWithFlags(&evFork, cudaEventDisableTiming);
        cudaEventCreateWithFlags(&evJoin, cudaEventDisableTiming);
    }

    cudaEventRecord(evFork, 0);
    cudaStreamWaitEvent(s1, evFork, 0);

    // --- s1: V branch ---
    {   // vpool = maxpool(wv @ x + bv)
        dim3 g(NSP / 128, CCH / 128, BATCH);
        mma_gemm_k<1><<<g, 256, 0, s1>>>(wv, x, bv, pvp, CCH, NSP, CCH);
    }
    {   // v' = wo @ vpool
        dim3 g(NPOOL / 128, CCH / 128, BATCH);
        mma_gemm_k<0><<<g, 256, 0, s1>>>(wo, pvp, nullptr, pvpr, CCH, NPOOL, CCH);
    }
    cudaEventRecord(evJoin, s1);

    // --- main: conv_qk (mma) -> energy (mma, exp->bf16) -> invden ---
    {
        dim3 g(NSP / 128, 1, BATCH);
        conv_qk_mma<<<g, 256>>>(wk, bk, wq, bq, x, pkT, pqT);
    }
    {
        dim3 g(NPOOL / 128, NSP / 128, BATCH);
        energy_mma<<<g, 256>>>(pkT, pqT, pattnh, ppart);
    }
    invden_k<<<BATCH * NPOOL / 256, 256>>>(ppart, pinv);

    cudaStreamWaitEvent(0, evJoin, 0);
    scale_v_k<<<BATCH * CCH * NPOOL / 256, 256>>>(pvpr, pinv, pvppb);
    {
        dim3 g(NSP / 128, 1, BATCH);
        final2_k<<<g, 256>>>(pvppb, pattnh, bo, gamma, x, out);
    }
}